// round 16
// baseline (speedup 1.0000x reference)
#include <cuda_runtime.h>
#include <cstdint>

// Problem constants
#define BB   128        // batch
#define IN_  1024
#define OUT_ 1024
#define NS   16         // i-dimension splits (empirical optimum)
#define LI   (IN_/NS)   // 64 i-values per split
#define NB   8          // batches per block (amortization sweet spot)
#define NBG  (BB/NB)    // 16 batch groups
#define OT   256        // outs per block
#define OTG  (OUT_/OT)  // 4 out groups
#define O4   (OUT_/4)   // 256 float4 lanes over full OUT
#define OT4  (OT/4)     // 64 float4 lanes per block
#define O8L  32         // float8 lanes per block (OT/8)
#define NTILE (NBG*OTG) // 64 (bg,z) tiles
#define NMAIN (NS*NTILE)// 1024 streaming blocks
#define NRED  1024      // reducer blocks (16 per tile)

// Scratch (allocation-free rule: __device__ globals; zero-init, self-reset)
__device__ float g_partial[NS * BB * OUT_];   // per-split partials, 8 MB
__device__ int   g_count[NTILE];              // producer arrivals per tile
__device__ int   g_done[NTILE];               // reducer completions per tile

// ---- 256-bit global memory ops (sm_100+: ld/st.global.v8.b32) ----
__device__ __forceinline__ void ld256_cs(const float* p, float* d) {
    asm volatile("ld.global.cs.v8.b32 {%0,%1,%2,%3,%4,%5,%6,%7}, [%8];"
        : "=f"(d[0]), "=f"(d[1]), "=f"(d[2]), "=f"(d[3]),
          "=f"(d[4]), "=f"(d[5]), "=f"(d[6]), "=f"(d[7])
        : "l"(p));
}
__device__ __forceinline__ void ld256(const float* p, float* d) {
    asm volatile("ld.global.v8.b32 {%0,%1,%2,%3,%4,%5,%6,%7}, [%8];"
        : "=f"(d[0]), "=f"(d[1]), "=f"(d[2]), "=f"(d[3]),
          "=f"(d[4]), "=f"(d[5]), "=f"(d[6]), "=f"(d[7])
        : "l"(p));
}
__device__ __forceinline__ void st256(float* p, const float* v) {
    asm volatile("st.global.v8.b32 [%0], {%1,%2,%3,%4,%5,%6,%7,%8};"
        :: "l"(p), "f"(v[0]), "f"(v[1]), "f"(v[2]), "f"(v[3]),
           "f"(v[4]), "f"(v[5]), "f"(v[6]), "f"(v[7])
        : "memory");
}

// ---------------------------------------------------------------------------
// Fused kernel (R15 structure) with the streaming loop converted to 256-bit
// granularity: thread = (g = t>>5 in 0..3 batch class, l = t&31 float8 lane),
// batches lb = g+4k (k=0,1), acc[2] x float8. eps: 2 LDG.256/iter (was 4
// LDG.128) — halves LSU issue + L1tex wavefronts per byte to feed DRAM
// better (R6-R15: DRAM only 78% active, issue 48%). occ 6 (reg headroom 85,
// no spill risk). Producers bx<NMAIN; spin-wait reducers bx>=NMAIN overlap
// the reduction with the streaming drain (bid-ordered scheduling => all
// producers precede reducers => deadlock-free).
// ---------------------------------------------------------------------------
__global__ __launch_bounds__(128, 6)
void fused_kernel(const float* __restrict__ x,
                  const float* __restrict__ mu,
                  const float* __restrict__ ro,
                  const float* __restrict__ eps,
                  const float* __restrict__ mu_bias,
                  const float* __restrict__ ro_bias,
                  const float* __restrict__ eps_bias,
                  float* __restrict__ out) {
    __shared__ float4 red[4][32];     // reducer combine buffer (2 KB)
    __shared__ float  xs[NB][LI];     // producer x tile (2 KB)

    const int bx = blockIdx.x;
    const int t  = threadIdx.x;

    if (bx >= NMAIN) {
        // =================== REDUCER ROLE (unchanged from R15) ============
        const int rb   = bx - NMAIN;          // 0..1023
        const int tile = rb >> 4;             // 0..63  (= bg*OTG + z)
        const int sub  = rb & 15;             // 0..15  slice of the tile
        const int bg   = tile >> 2;
        const int z    = tile & (OTG - 1);
        const int b0   = bg * NB;

        if (t == 0) {
            while (atomicAdd(&g_count[tile], 0) < NS)
                __nanosleep(200);
        }
        __syncthreads();
        __threadfence();                      // acquire partials

        const int lane = t & 31;
        const int q    = t >> 5;              // 0..3 s-quarter
        const int e    = sub * 32 + lane;     // entry in [0,512)
        const int lb   = e >> 6;              // 0..7 batch in tile
        const int oc   = z * OT4 + (e & 63);  // float4 column
        const size_t L = (size_t)(b0 + lb) * O4 + oc;

        const float4* Pc = reinterpret_cast<const float4*>(g_partial) + L;

        float4 r = Pc[(size_t)(q * 4) * BB * O4];
#pragma unroll
        for (int j = 1; j < 4; j++) {
            float4 p = Pc[(size_t)(q * 4 + j) * BB * O4];
            r.x += p.x; r.y += p.y; r.z += p.z; r.w += p.w;
        }
        red[q][lane] = r;
        __syncthreads();

        if (q == 0) {
            float4 a = red[0][lane];
#pragma unroll
            for (int j = 1; j < 4; j++) {
                float4 p = red[j][lane];
                a.x += p.x; a.y += p.y; a.z += p.z; a.w += p.w;
            }
            reinterpret_cast<float4*>(out)[L] = a;
        }

        __syncthreads();
        if (t == 0) {
            int d = atomicAdd(&g_done[tile], 1);
            if (d == 15) {
                atomicExch(&g_count[tile], 0);
                atomicExch(&g_done[tile], 0);
            }
        }
        return;
    }

    // =================== PRODUCER ROLE (256-bit streaming loop) ==========
    const int s  = bx & (NS - 1);         // 0..15
    const int bg = (bx >> 4) & (NBG - 1); // 0..15
    const int z  = bx >> 8;               // 0..3
    const int l  = t & (O8L - 1);         // float8 lane (0..31)
    const int g  = t >> 5;                // 0..3 batch class
    const int i0 = s * LI;
    const int b0 = bg * NB;
    const int o0 = z * OT + l * 8;        // first float of this thread's slice

    // Cooperative float4 load of x tile [8 b][64 i]
    {
        const int row = t >> 4;           // 0..7
        const int col = (t & 15) * 4;     // 0..60
        float4 v = *reinterpret_cast<const float4*>(
            x + (size_t)(b0 + row) * IN_ + i0 + col);
        *reinterpret_cast<float4*>(&xs[row][col]) = v;
    }
    __syncthreads();

    const float* muP = mu  + (size_t)i0 * OUT_ + o0;
    const float* roP = ro  + (size_t)i0 * OUT_ + o0;
    const float* epP = eps + ((size_t)b0 * IN_ + i0) * OUT_ + o0;

    float acc[2][8];

    // ---- ii = 0 peeled: pure multiply (initializes acc) ----
    {
        float ev0[8], ev1[8], rr[8], mw[8], sg[8];
        ld256_cs(epP + (size_t)g * IN_ * OUT_, ev0);
        ld256_cs(epP + (size_t)(g + 4) * IN_ * OUT_, ev1);
        ld256(roP, rr);
        ld256(muP, mw);
#pragma unroll
        for (int j = 0; j < 8; j++) sg[j] = log1pf(__expf(rr[j]));
        const float x0 = xs[g][0];
        const float x1 = xs[g + 4][0];
#pragma unroll
        for (int j = 0; j < 8; j++) {
            acc[0][j] = x0 * fmaf(ev0[j], sg[j], mw[j]);
            acc[1][j] = x1 * fmaf(ev1[j], sg[j], mw[j]);
        }
    }

    // ---- ii = 1 .. LI-1 ----
#pragma unroll 1
    for (int ii = 1; ii < LI; ii++) {
        float ev0[8], ev1[8], rr[8], mw[8], sg[8];
        ld256_cs(epP + ((size_t)g * IN_ + ii) * OUT_, ev0);
        ld256_cs(epP + ((size_t)(g + 4) * IN_ + ii) * OUT_, ev1);
        ld256(roP + (size_t)ii * OUT_, rr);
        ld256(muP + (size_t)ii * OUT_, mw);
#pragma unroll
        for (int j = 0; j < 8; j++) sg[j] = log1pf(__expf(rr[j]));
        const float x0 = xs[g][ii];
        const float x1 = xs[g + 4][ii];
#pragma unroll
        for (int j = 0; j < 8; j++) {
            acc[0][j] = fmaf(x0, fmaf(ev0[j], sg[j], mw[j]), acc[0][j]);
            acc[1][j] = fmaf(x1, fmaf(ev1[j], sg[j], mw[j]), acc[1][j]);
        }
    }

    // ---- s==0 blocks fold in the bias term ----
    if (s == 0) {
        float rb[8], mb[8], sb[8], eb0[8], eb1[8];
        ld256(ro_bias + o0, rb);
        ld256(mu_bias + o0, mb);
        ld256(eps_bias + (size_t)(b0 + g) * OUT_ + o0, eb0);
        ld256(eps_bias + (size_t)(b0 + g + 4) * OUT_ + o0, eb1);
#pragma unroll
        for (int j = 0; j < 8; j++) sb[j] = log1pf(__expf(rb[j]));
#pragma unroll
        for (int j = 0; j < 8; j++) {
            acc[0][j] = fmaf(eb0[j], sb[j], acc[0][j] + mb[j]);
            acc[1][j] = fmaf(eb1[j], sb[j], acc[1][j] + mb[j]);
        }
    }

    // ---- write partials P[s][b][o] (256-bit), then signal arrival ----
    st256(g_partial + ((size_t)s * BB + b0 + g) * OUT_ + o0, acc[0]);
    st256(g_partial + ((size_t)s * BB + b0 + g + 4) * OUT_ + o0, acc[1]);

    __threadfence();                      // release own partial stores
    __syncthreads();                      // all threads fenced
    if (t == 0)
        atomicAdd(&g_count[bg * OTG + z], 1);
}

// ---------------------------------------------------------------------------
// Launch. Input order (metadata): x, mu, ro, mu_bias, ro_bias, eps, eps_bias
// ---------------------------------------------------------------------------
extern "C" void kernel_launch(void* const* d_in, const int* in_sizes, int n_in,
                              void* d_out, int out_size) {
    const float* x        = (const float*)d_in[0];
    const float* mu       = (const float*)d_in[1];
    const float* ro       = (const float*)d_in[2];
    const float* mu_bias  = (const float*)d_in[3];
    const float* ro_bias  = (const float*)d_in[4];
    const float* eps      = (const float*)d_in[5];
    const float* eps_bias = (const float*)d_in[6];
    float* out = (float*)d_out;

    // One kernel: 1024 producers + 1024 spin-wait reducers, 128 threads, occ 6
    fused_kernel<<<NMAIN + NRED, 128>>>(x, mu, ro, eps,
                                        mu_bias, ro_bias, eps_bias, out);
}

// round 17
// speedup vs baseline: 1.6923x; 1.6923x over previous
#include <cuda_runtime.h>
#include <cstdint>

// Problem constants
#define BB   128        // batch
#define IN_  1024
#define OUT_ 1024
#define NS   16         // i-dimension splits (empirical optimum)
#define LI   (IN_/NS)   // 64 i-values per split
#define NB   8          // batches per block (amortization sweet spot)
#define NBG  (BB/NB)    // 16 batch groups
#define OT   256        // outs per block
#define OTG  (OUT_/OT)  // 4 out groups
#define O4   (OUT_/4)   // 256 float4 lanes over full OUT
#define OT4  (OT/4)     // 64 float4 lanes per block
#define NTILE (NBG*OTG) // 64 (bg,z) tiles
#define NMAIN (NS*NTILE)// 1024 streaming blocks
#define NRED  1024      // reducer blocks (16 per tile)

// Scratch (allocation-free rule: __device__ globals; zero-init, self-reset)
__device__ float g_partial[NS * BB * OUT_];   // per-split partials, 8 MB
__device__ int   g_count[NTILE];              // producer arrivals per tile
__device__ int   g_done[NTILE];               // reducer completions per tile

// ---------------------------------------------------------------------------
// Session-best configuration (R15, 86.43us — final). Single kernel, two
// roles by blockIdx:
//   bx <  NMAIN: streaming block (s,bg,z) — NS=16, NB=8, OT=256, 128 thr,
//                occ 7, float4 loads, acc[4]. Measured optimum across
//                NB{4,8,16}, OT{64..1024}, occ{2,6,7,8}, NS{16,32}, smem-acc,
//                and v8.b32 variants (all slower; v8 regressed 1.7x).
//   bx >= NMAIN: reducer block — spins (nanosleep) until its tile's 16
//                producers arrived, then does a 32-float4 slice of the
//                4-way-split s-sum in fixed s-order (deterministic).
// Wave 1 = 148*7 = 1036 slots >= 1024 producers, and bid-ordered scheduling
// puts all producers first -> deadlock-free. Reducers overlap the streaming
// drain tail, hiding most of the 5.5us reduce floor (shown in R9-R14 to be
// immune to layout/PDL/atomics/L2-policy). Dual counters self-reset for
// graph replay. softplus(ro) fused; bias folded into s==0 partials; eps via
// __ldcs (evict-first).
// ---------------------------------------------------------------------------
__global__ __launch_bounds__(128, 7)
void fused_kernel(const float* __restrict__ x,
                  const float* __restrict__ mu,
                  const float* __restrict__ ro,
                  const float* __restrict__ eps,
                  const float* __restrict__ mu_bias,
                  const float* __restrict__ ro_bias,
                  const float* __restrict__ eps_bias,
                  float* __restrict__ out) {
    __shared__ float4 red[4][32];     // reducer combine buffer (2 KB)
    __shared__ float  xs[NB][LI];     // producer x tile (2 KB)

    const int bx = blockIdx.x;
    const int t  = threadIdx.x;

    if (bx >= NMAIN) {
        // =================== REDUCER ROLE ===================
        const int rb   = bx - NMAIN;          // 0..1023
        const int tile = rb >> 4;             // 0..63  (= bg*OTG + z)
        const int sub  = rb & 15;             // 0..15  slice of the tile
        const int bg   = tile >> 2;
        const int z    = tile & (OTG - 1);
        const int b0   = bg * NB;

        // Spin until all NS producers of this tile arrived
        if (t == 0) {
            while (atomicAdd(&g_count[tile], 0) < NS)
                __nanosleep(200);
        }
        __syncthreads();
        __threadfence();                      // acquire partials

        const int lane = t & 31;
        const int q    = t >> 5;              // 0..3 s-quarter
        const int e    = sub * 32 + lane;     // entry in [0,512)
        const int lb   = e >> 6;              // 0..7 batch in tile
        const int oc   = z * OT4 + (e & 63);  // float4 column
        const size_t L = (size_t)(b0 + lb) * O4 + oc;

        const float4* Pc = reinterpret_cast<const float4*>(g_partial) + L;

        // Fixed ascending order within quarter
        float4 r = Pc[(size_t)(q * 4) * BB * O4];
#pragma unroll
        for (int j = 1; j < 4; j++) {
            float4 p = Pc[(size_t)(q * 4 + j) * BB * O4];
            r.x += p.x; r.y += p.y; r.z += p.z; r.w += p.w;
        }
        red[q][lane] = r;
        __syncthreads();

        if (q == 0) {
            // Fixed quarter order -> deterministic
            float4 a = red[0][lane];
#pragma unroll
            for (int j = 1; j < 4; j++) {
                float4 p = red[j][lane];
                a.x += p.x; a.y += p.y; a.z += p.z; a.w += p.w;
            }
            reinterpret_cast<float4*>(out)[L] = a;
        }

        // Completion + counter reset for next graph replay
        __syncthreads();
        if (t == 0) {
            int d = atomicAdd(&g_done[tile], 1);
            if (d == 15) {                    // last reducer of this tile
                atomicExch(&g_count[tile], 0);
                atomicExch(&g_done[tile], 0);
            }
        }
        return;
    }

    // =================== PRODUCER ROLE (proven streaming loop) ===========
    const int s  = bx & (NS - 1);         // 0..15
    const int bg = (bx >> 4) & (NBG - 1); // 0..15
    const int z  = bx >> 8;               // 0..3
    const int l  = t & (OT4 - 1);         // o float4 lane (0..63)
    const int g  = t >> 6;                // 0..1 batch class
    const int i0 = s * LI;
    const int b0 = bg * NB;
    const int oc = z * OT4 + l;           // float4 column in [0, O4)

    // Cooperative float4 load of x tile [8 b][64 i]
    {
        const int row = t >> 4;           // 0..7
        const int col = (t & 15) * 4;     // 0..60
        float4 v = *reinterpret_cast<const float4*>(
            x + (size_t)(b0 + row) * IN_ + i0 + col);
        *reinterpret_cast<float4*>(&xs[row][col]) = v;
    }
    __syncthreads();

    const float4* mu4 = reinterpret_cast<const float4*>(mu)  + (size_t)i0 * O4 + oc;
    const float4* ro4 = reinterpret_cast<const float4*>(ro)  + (size_t)i0 * O4 + oc;
    const float4* ep4 = reinterpret_cast<const float4*>(eps)
                        + ((size_t)b0 * IN_ + i0) * O4 + oc;

    float4 acc[4];

    // ---- ii = 0 peeled: pure multiply (initializes acc) ----
    {
        float4 ev[4];
#pragma unroll
        for (int k = 0; k < 4; k++) {
            const int lb = g + 2 * k;
            ev[k] = __ldcs(&ep4[(size_t)lb * IN_ * O4]);
        }
        const float4 rr = ro4[0];
        const float4 mw = mu4[0];
        float4 sg;
        sg.x = log1pf(__expf(rr.x));
        sg.y = log1pf(__expf(rr.y));
        sg.z = log1pf(__expf(rr.z));
        sg.w = log1pf(__expf(rr.w));
#pragma unroll
        for (int k = 0; k < 4; k++) {
            const int lb = g + 2 * k;
            const float xr = xs[lb][0];
            acc[k].x = xr * fmaf(ev[k].x, sg.x, mw.x);
            acc[k].y = xr * fmaf(ev[k].y, sg.y, mw.y);
            acc[k].z = xr * fmaf(ev[k].z, sg.z, mw.z);
            acc[k].w = xr * fmaf(ev[k].w, sg.w, mw.w);
        }
    }

    // ---- ii = 1 .. LI-1 ----
#pragma unroll 1
    for (int ii = 1; ii < LI; ii++) {
        float4 ev[4];
#pragma unroll
        for (int k = 0; k < 4; k++) {
            const int lb = g + 2 * k;
            ev[k] = __ldcs(&ep4[((size_t)lb * IN_ + ii) * O4]);
        }
        const float4 rr = ro4[(size_t)ii * O4];
        const float4 mw = mu4[(size_t)ii * O4];
        float4 sg;
        sg.x = log1pf(__expf(rr.x));
        sg.y = log1pf(__expf(rr.y));
        sg.z = log1pf(__expf(rr.z));
        sg.w = log1pf(__expf(rr.w));
#pragma unroll
        for (int k = 0; k < 4; k++) {
            const int lb = g + 2 * k;
            const float xr = xs[lb][ii];
            acc[k].x = fmaf(xr, fmaf(ev[k].x, sg.x, mw.x), acc[k].x);
            acc[k].y = fmaf(xr, fmaf(ev[k].y, sg.y, mw.y), acc[k].y);
            acc[k].z = fmaf(xr, fmaf(ev[k].z, sg.z, mw.z), acc[k].z);
            acc[k].w = fmaf(xr, fmaf(ev[k].w, sg.w, mw.w), acc[k].w);
        }
    }

    // ---- s==0 blocks fold in the bias term ----
    if (s == 0) {
        const float4 rb = reinterpret_cast<const float4*>(ro_bias)[oc];
        const float4 mb = reinterpret_cast<const float4*>(mu_bias)[oc];
        float4 sb;
        sb.x = log1pf(__expf(rb.x));
        sb.y = log1pf(__expf(rb.y));
        sb.z = log1pf(__expf(rb.z));
        sb.w = log1pf(__expf(rb.w));
#pragma unroll
        for (int k = 0; k < 4; k++) {
            const int lb = g + 2 * k;
            const float4 eb = reinterpret_cast<const float4*>(eps_bias)
                                  [(size_t)(b0 + lb) * O4 + oc];
            acc[k].x = fmaf(eb.x, sb.x, acc[k].x + mb.x);
            acc[k].y = fmaf(eb.y, sb.y, acc[k].y + mb.y);
            acc[k].z = fmaf(eb.z, sb.z, acc[k].z + mb.z);
            acc[k].w = fmaf(eb.w, sb.w, acc[k].w + mb.w);
        }
    }

    // ---- write partials P[s][b][o], then signal arrival ----
    float4* Pbase = reinterpret_cast<float4*>(g_partial);
#pragma unroll
    for (int k = 0; k < 4; k++) {
        const int lb = g + 2 * k;
        Pbase[((size_t)s * BB + b0 + lb) * O4 + oc] = acc[k];
    }
    __threadfence();                      // release own partial stores
    __syncthreads();                      // all threads fenced
    if (t == 0)
        atomicAdd(&g_count[bg * OTG + z], 1);
}

// ---------------------------------------------------------------------------
// Launch. Input order (metadata): x, mu, ro, mu_bias, ro_bias, eps, eps_bias
// ---------------------------------------------------------------------------
extern "C" void kernel_launch(void* const* d_in, const int* in_sizes, int n_in,
                              void* d_out, int out_size) {
    const float* x        = (const float*)d_in[0];
    const float* mu       = (const float*)d_in[1];
    const float* ro       = (const float*)d_in[2];
    const float* mu_bias  = (const float*)d_in[3];
    const float* ro_bias  = (const float*)d_in[4];
    const float* eps      = (const float*)d_in[5];
    const float* eps_bias = (const float*)d_in[6];
    float* out = (float*)d_out;

    // One kernel: 1024 producers + 1024 spin-wait reducers, 128 threads, occ 7
    fused_kernel<<<NMAIN + NRED, 128>>>(x, mu, ro, eps,
                                        mu_bias, ro_bias, eps_bias, out);
}